// round 1
// baseline (speedup 1.0000x reference)
#include <cuda_runtime.h>
#include <math.h>

// Problem constants (fixed by reference): B=2, C=128, H=W=128, outc=128, KS=3, N=9, PAD=1
#define Bn 2
#define Cn 128
#define Hh 128
#define Ww 128
#define OC 128

// -------- scratch (static device globals; no allocation allowed) --------
__device__ float  g_xt [Bn*Hh*Ww*Cn];     // x transposed to [B,H,W,C]  (16.8 MB)
__device__ float  g_om [Bn*Hh*Ww*27];     // per-pixel: 18 offsets + 9 sigmoid(mask), [B,H,W,27]
__device__ float4 g_wt4[9*32*128];        // w_conv as [k=di*3+dj][c4][o] float4 over c
__device__ float  g_wpm[27*9*128];        // w_p/w_m as [oc27][kh*3+kw][c]

// ---------------------------------------------------------------
// Kernel 0a: transpose x NCHW -> BHWC (coalesced both directions)
// grid (W/32=4, C/32=4, B*H=256), block (32,8)
__global__ void k_transpose_x(const float* __restrict__ x) {
    __shared__ float tile[32][33];
    int bxw = blockIdx.x, byc = blockIdx.y, bz = blockIdx.z;
    int b = bz >> 7, h = bz & 127;
    int tx = threadIdx.x, ty = threadIdx.y;
#pragma unroll
    for (int i = 0; i < 4; i++) {
        int c = byc * 32 + ty + i * 8;
        tile[ty + i * 8][tx] = x[((b * Cn + c) * Hh + h) * Ww + bxw * 32 + tx];
    }
    __syncthreads();
#pragma unroll
    for (int i = 0; i < 4; i++) {
        int w = bxw * 32 + ty + i * 8;
        g_xt[((b * Hh + h) * Ww + w) * Cn + byc * 32 + tx] = tile[tx][ty + i * 8];
    }
}

// ---------------------------------------------------------------
// Kernel 0b: weight re-layouts (tiny)
__global__ void k_transpose_w(const float* __restrict__ w_conv,
                              const float* __restrict__ w_p,
                              const float* __restrict__ w_m) {
    int t = blockIdx.x * blockDim.x + threadIdx.x;
    if (t < 9 * 32 * 128 * 4) {
        // g_wt4 flat float index: ((k*32+c4)*128+o)*4+j  with c=c4*4+j
        int j  = t & 3;
        int o  = (t >> 2) & 127;
        int c4 = (t >> 9) & 31;
        int k  = t >> 14;
        int c  = c4 * 4 + j;
        int di = k / 3, dj = k - di * 3;
        ((float*)g_wt4)[t] = w_conv[((o * Cn + c) * 3 + di) * 3 + dj];
    } else {
        int t2 = t - 9 * 32 * 128 * 4;
        if (t2 < 27 * 9 * 128) {
            int c  = t2 & 127;
            int idx = t2 >> 7;
            int t9 = idx % 9;
            int oc = idx / 9;
            int kh = t9 / 3, kw = t9 - kh * 3;
            float val;
            if (oc < 18) val = w_p[((oc * Cn + c) * 3 + kh) * 3 + kw];
            else         val = w_m[(((oc - 18) * Cn + c) * 3 + kh) * 3 + kw];
            g_wpm[t2] = val;
        }
    }
}

// ---------------------------------------------------------------
// Kernel A: fused offset(18) + mask(9) 3x3 conv, pad 1.
// grid (8,8,2), block 256 (one thread per pixel of a 16x16 tile).
// smem: x tile (18*18*36 floats, padded stride 36 to dodge bank conflicts)
//       + weight chunk (27*9*32 floats).
__global__ void k_convA(const float* __restrict__ b_p, const float* __restrict__ b_m) {
    extern __shared__ float smem[];
    float* xs = smem;           // 11664 floats
    float* ws = smem + 11664;   // 7776 floats
    int b  = blockIdx.z;
    int h0 = blockIdx.y * 16, w0 = blockIdx.x * 16;
    int tid = threadIdx.x;
    int px = tid & 15, py = tid >> 4;

    float acc[27];
#pragma unroll
    for (int i = 0; i < 27; i++) acc[i] = 0.f;

    for (int cc = 0; cc < Cn; cc += 32) {
        // load 18x18x32 input tile (channel-last)
        for (int e = tid; e < 18 * 18 * 32; e += 256) {
            int c   = e & 31;
            int col = (e >> 5) % 18;
            int row = e / (18 * 32);
            int gh = h0 - 1 + row, gw = w0 - 1 + col;
            float val = 0.f;
            if (gh >= 0 && gh < Hh && gw >= 0 && gw < Ww)
                val = g_xt[((b * Hh + gh) * Ww + gw) * Cn + cc + c];
            xs[(row * 18 + col) * 36 + c] = val;
        }
        // load weight chunk: ws[(oc*9+t9)*32 + c]
        for (int e = tid; e < 27 * 9 * 32; e += 256)
            ws[e] = g_wpm[(e >> 5) * 128 + cc + (e & 31)];
        __syncthreads();

#pragma unroll 1
        for (int t9 = 0; t9 < 9; t9++) {
            int kh = t9 / 3, kw = t9 - kh * 3;
            const float* xb = &xs[((py + kh) * 18 + (px + kw)) * 36];
#pragma unroll 1
            for (int c4 = 0; c4 < 8; c4++) {
                float4 x4 = *(const float4*)(xb + c4 * 4);
#pragma unroll
                for (int oc = 0; oc < 27; oc++) {
                    float4 w4 = *(const float4*)(&ws[(oc * 9 + t9) * 32 + c4 * 4]);
                    acc[oc] += x4.x * w4.x + x4.y * w4.y + x4.z * w4.z + x4.w * w4.w;
                }
            }
        }
        __syncthreads();
    }

    int h = h0 + py, w = w0 + px;
    float* dst = &g_om[((b * Hh + h) * Ww + w) * 27];
#pragma unroll
    for (int ch = 0; ch < 18; ch++) dst[ch] = acc[ch] + b_p[ch];
#pragma unroll
    for (int n = 0; n < 9; n++) {
        float t = acc[18 + n] + b_m[n];
        dst[18 + n] = 1.f / (1.f + expf(-t));
    }
}

// ---------------------------------------------------------------
// Kernel B: fused deformable bilinear sampling + modulation + final 3x3/stride-3 conv.
// grid (32,32,2): each block = 4x4 output pixels, all 128 out channels.
// Phase 1: build v[16 px][9 taps][128 c] in smem (bilinear-gathered, modulated).
// Phase 2: out[o,px] = sum_{k,c} Wt[k,c,o] * v[px,k,c]   (FFMA GEMM)
__global__ void k_deform(float* __restrict__ out) {
    extern __shared__ float v[];  // 16*9*128 = 18432 floats
    int b   = blockIdx.z;
    int oh0 = blockIdx.y * 4, ow0 = blockIdx.x * 4;
    int tid  = threadIdx.x;
    int lane = tid & 31, wi = tid >> 5;

    // ---- phase 1: 144 units = (pixel, tap), one warp per unit ----
    for (int u = wi; u < 144; u += 8) {
        int p = u / 9, k = u - p * 9;
        int ly = p >> 2, lx = p & 3;
        int oh = oh0 + ly, ow = ow0 + lx;
        int di = k / 3, dj = k - di * 3;
        // final-conv tap (di,dj) -> source pixel delta + sampling-grid index n
        int dh = (di == 0) ? -1 : 0;
        int iI = (di == 0) ? 2 : (di == 1 ? 0 : 1);
        int dw = (dj == 0) ? -1 : 0;
        int jJ = (dj == 0) ? 2 : (dj == 1 ? 0 : 1);
        int h = oh + dh, w = ow + dw;
        float* vd = &v[u * 128];
        if (h < 0 || w < 0) {  // conv zero-padding row/col
            for (int ci = lane; ci < 128; ci += 32) vd[ci] = 0.f;
            continue;
        }
        int n = iI * 3 + jJ;
        const float* om = &g_om[((b * Hh + h) * Ww + w) * 27];
        float offx = om[n], offy = om[9 + n], mval = om[18 + n];
        float p_x = offx + (float)(iI - 1) + (float)(h + 1);
        float p_y = offy + (float)(jJ - 1) + (float)(w + 1);
        float flx = floorf(p_x), fly = floorf(p_y);
        float ltx = fminf(fmaxf(flx, 0.f), 129.f);
        float lty = fminf(fmaxf(fly, 0.f), 129.f);
        float rbx = fminf(fmaxf(flx + 1.f, 0.f), 129.f);
        float rby = fminf(fmaxf(fly + 1.f, 0.f), 129.f);
        float cpx = fminf(fmaxf(p_x, 0.f), 129.f);
        float cpy = fminf(fmaxf(p_y, 0.f), 129.f);
        float ax  = 1.f + (ltx - cpx);
        float bx_ = 1.f - (rbx - cpx);
        float ay  = 1.f + (lty - cpy);
        float by_ = 1.f - (rby - cpy);
        float wq[4] = { ax * ay * mval, bx_ * by_ * mval, ax * by_ * mval, bx_ * ay * mval };
        float qxf[4] = { ltx, rbx, ltx, rbx };
        float qyf[4] = { lty, rby, rby, lty };
        int base[4];
#pragma unroll
        for (int j = 0; j < 4; j++) {
            int ix = (int)qxf[j], iy = (int)qyf[j];
            bool valid = (ix >= 1 && ix <= Hh && iy >= 1 && iy <= Ww);
            base[j] = valid ? (((b * Hh + ix - 1) * Ww + iy - 1) * Cn) : 0;
            if (!valid) wq[j] = 0.f;  // padded region is zero
        }
#pragma unroll
        for (int ci0 = 0; ci0 < 128; ci0 += 32) {
            int ci = ci0 + lane;
            float s = wq[0] * g_xt[base[0] + ci] + wq[1] * g_xt[base[1] + ci]
                    + wq[2] * g_xt[base[2] + ci] + wq[3] * g_xt[base[3] + ci];
            vd[ci] = s;
        }
    }
    __syncthreads();

    // ---- phase 2: GEMM. thread = (o, pixel-group of 8) ----
    int o  = tid & 127;
    int pg = tid >> 7;  // 0 or 1
    float acc[8];
#pragma unroll
    for (int q = 0; q < 8; q++) acc[q] = 0.f;

#pragma unroll 1
    for (int k = 0; k < 9; k++) {
        const float4* wk = &g_wt4[k * 32 * 128 + o];
        const float*  vk = &v[(pg * 8 * 9 + k) * 128];
#pragma unroll 1
        for (int c4 = 0; c4 < 32; c4++) {
            float4 w4 = wk[c4 * 128];  // coalesced over o
#pragma unroll
            for (int q = 0; q < 8; q++) {
                float4 v4 = *(const float4*)(&vk[q * 9 * 128 + c4 * 4]);  // broadcast LDS
                acc[q] += v4.x * w4.x + v4.y * w4.y + v4.z * w4.z + v4.w * w4.w;
            }
        }
    }

    // write: q0..3 -> row oh0+pg*2, cols ow0..ow0+3 ; q4..7 -> next row
    int ohA = oh0 + pg * 2;
    float4 r0 = make_float4(acc[0], acc[1], acc[2], acc[3]);
    float4 r1 = make_float4(acc[4], acc[5], acc[6], acc[7]);
    *(float4*)&out[((b * OC + o) * Hh + ohA)     * Ww + ow0] = r0;
    *(float4*)&out[((b * OC + o) * Hh + ohA + 1) * Ww + ow0] = r1;
}

// ---------------------------------------------------------------
extern "C" void kernel_launch(void* const* d_in, const int* in_sizes, int n_in,
                              void* d_out, int out_size) {
    const float* x      = (const float*)d_in[0];
    const float* w_p    = (const float*)d_in[1];
    const float* b_p    = (const float*)d_in[2];
    const float* w_m    = (const float*)d_in[3];
    const float* b_m    = (const float*)d_in[4];
    const float* w_conv = (const float*)d_in[5];
    float* out = (float*)d_out;

    cudaFuncSetAttribute(k_convA,  cudaFuncAttributeMaxDynamicSharedMemorySize, (11664 + 7776) * 4);
    cudaFuncSetAttribute(k_deform, cudaFuncAttributeMaxDynamicSharedMemorySize, 18432 * 4);

    k_transpose_x<<<dim3(4, 4, Bn * Hh), dim3(32, 8)>>>(x);

    int wthreads = 9 * 32 * 128 * 4 + 27 * 9 * 128;
    k_transpose_w<<<(wthreads + 255) / 256, 256>>>(w_conv, w_p, w_m);

    k_convA<<<dim3(8, 8, Bn), 256, (11664 + 7776) * 4>>>(b_p, b_m);

    k_deform<<<dim3(32, 32, Bn), 256, 18432 * 4>>>(out);
}

// round 2
// speedup vs baseline: 1.0729x; 1.0729x over previous
#include <cuda_runtime.h>
#include <math.h>

// Problem constants (fixed by reference): B=2, C=128, H=W=128, outc=128, KS=3, N=9, PAD=1
#define Bn 2
#define Cn 128
#define Hh 128
#define Ww 128
#define OC 128

typedef unsigned long long u64;
typedef unsigned int u32;

// -------- scratch (static device globals; no allocation allowed) --------
__device__ float  g_xt [Bn*Hh*Ww*Cn];     // x transposed to [B,H,W,C]  (16.8 MB)
__device__ float  g_om [Bn*Hh*Ww*27];     // per-pixel: 18 offsets + 9 sigmoid(mask)
__device__ float4 g_wt4[9*32*128];        // w_conv as [k][c4][o] float4 over c
__device__ float  g_wpm[27*9*128];        // w_p/w_m as [oc27][kh*3+kw][c]

__device__ __forceinline__ u32 smem_u32(const void* p) {
    u32 a;
    asm("{ .reg .u64 t; cvta.to.shared.u64 t, %1; cvt.u32.u64 %0, t; }" : "=r"(a) : "l"(p));
    return a;
}

// ---------------------------------------------------------------
// Kernel 0a: transpose x NCHW -> BHWC
__global__ void k_transpose_x(const float* __restrict__ x) {
    __shared__ float tile[32][33];
    int bxw = blockIdx.x, byc = blockIdx.y, bz = blockIdx.z;
    int b = bz >> 7, h = bz & 127;
    int tx = threadIdx.x, ty = threadIdx.y;
#pragma unroll
    for (int i = 0; i < 4; i++) {
        int c = byc * 32 + ty + i * 8;
        tile[ty + i * 8][tx] = x[((b * Cn + c) * Hh + h) * Ww + bxw * 32 + tx];
    }
    __syncthreads();
#pragma unroll
    for (int i = 0; i < 4; i++) {
        int w = bxw * 32 + ty + i * 8;
        g_xt[((b * Hh + h) * Ww + w) * Cn + byc * 32 + tx] = tile[tx][ty + i * 8];
    }
}

// ---------------------------------------------------------------
// Kernel 0b: weight re-layouts (tiny)
__global__ void k_transpose_w(const float* __restrict__ w_conv,
                              const float* __restrict__ w_p,
                              const float* __restrict__ w_m) {
    int t = blockIdx.x * blockDim.x + threadIdx.x;
    if (t < 9 * 32 * 128 * 4) {
        int j  = t & 3;
        int o  = (t >> 2) & 127;
        int c4 = (t >> 9) & 31;
        int k  = t >> 14;
        int c  = c4 * 4 + j;
        int di = k / 3, dj = k - di * 3;
        ((float*)g_wt4)[t] = w_conv[((o * Cn + c) * 3 + di) * 3 + dj];
    } else {
        int t2 = t - 9 * 32 * 128 * 4;
        if (t2 < 27 * 9 * 128) {
            int c  = t2 & 127;
            int idx = t2 >> 7;
            int t9 = idx % 9;
            int oc = idx / 9;
            int kh = t9 / 3, kw = t9 - kh * 3;
            float val;
            if (oc < 18) val = w_p[((oc * Cn + c) * 3 + kh) * 3 + kw];
            else         val = w_m[(((oc - 18) * Cn + c) * 3 + kh) * 3 + kw];
            g_wpm[t2] = val;
        }
    }
}

// ---------------------------------------------------------------
// Kernel A: fused offset(18) + mask(9) 3x3 conv, pad 1. FFMA2 (f32x2) inner loop.
__global__ void k_convA(const float* __restrict__ b_p, const float* __restrict__ b_m) {
    extern __shared__ float smem[];
    float* xs = smem;           // 11664 floats
    float* ws = smem + 11664;   // 7776 floats
    u32 xsb = smem_u32(xs);
    u32 wsb = smem_u32(ws);
    int b  = blockIdx.z;
    int h0 = blockIdx.y * 16, w0 = blockIdx.x * 16;
    int tid = threadIdx.x;
    int px = tid & 15, py = tid >> 4;

    u64 acc2[27];  // f32x2 accumulators: {even-c partial, odd-c partial}
#pragma unroll
    for (int i = 0; i < 27; i++) acc2[i] = 0ull;

    for (int cc = 0; cc < Cn; cc += 32) {
        for (int e = tid; e < 18 * 18 * 32; e += 256) {
            int c   = e & 31;
            int col = (e >> 5) % 18;
            int row = e / (18 * 32);
            int gh = h0 - 1 + row, gw = w0 - 1 + col;
            float val = 0.f;
            if (gh >= 0 && gh < Hh && gw >= 0 && gw < Ww)
                val = g_xt[((b * Hh + gh) * Ww + gw) * Cn + cc + c];
            xs[(row * 18 + col) * 36 + c] = val;
        }
        for (int e = tid; e < 27 * 9 * 32; e += 256)
            ws[e] = g_wpm[(e >> 5) * 128 + cc + (e & 31)];
        __syncthreads();

#pragma unroll 1
        for (int t9 = 0; t9 < 9; t9++) {
            int kh = t9 / 3, kw = t9 - kh * 3;
            u32 xaddr = xsb + (((py + kh) * 18 + (px + kw)) * 36) * 4;
#pragma unroll 1
            for (int c4 = 0; c4 < 8; c4++) {
                u64 x01, x23;
                asm("ld.shared.v2.u64 {%0,%1}, [%2];"
                    : "=l"(x01), "=l"(x23) : "r"(xaddr + c4 * 16));
#pragma unroll
                for (int oc = 0; oc < 27; oc++) {
                    u64 w01, w23;
                    asm("ld.shared.v2.u64 {%0,%1}, [%2];"
                        : "=l"(w01), "=l"(w23)
                        : "r"(wsb + ((oc * 9 + t9) * 32 + c4 * 4) * 4));
                    asm("fma.rn.f32x2 %0, %1, %2, %0;" : "+l"(acc2[oc]) : "l"(x01), "l"(w01));
                    asm("fma.rn.f32x2 %0, %1, %2, %0;" : "+l"(acc2[oc]) : "l"(x23), "l"(w23));
                }
            }
        }
        __syncthreads();
    }

    float acc[27];
#pragma unroll
    for (int i = 0; i < 27; i++) {
        float lo, hi;
        asm("mov.b64 {%0,%1}, %2;" : "=f"(lo), "=f"(hi) : "l"(acc2[i]));
        acc[i] = lo + hi;
    }

    int h = h0 + py, w = w0 + px;
    float* dst = &g_om[((b * Hh + h) * Ww + w) * 27];
#pragma unroll
    for (int ch = 0; ch < 18; ch++) dst[ch] = acc[ch] + b_p[ch];
#pragma unroll
    for (int n = 0; n < 9; n++) {
        float t = acc[18 + n] + b_m[n];
        dst[18 + n] = 1.f / (1.f + expf(-t));
    }
}

// ---------------------------------------------------------------
// Kernel B: deformable bilinear sampling + modulation + final 3x3/stride-3 conv.
// Phase 1: float4 gathers. Phase 2: FFMA2 (f32x2) GEMM.
__global__ void k_deform(float* __restrict__ out) {
    extern __shared__ float v[];  // 16*9*128 = 18432 floats
    u32 vbase = smem_u32(v);
    int b   = blockIdx.z;
    int oh0 = blockIdx.y * 4, ow0 = blockIdx.x * 4;
    int tid  = threadIdx.x;
    int lane = tid & 31, wi = tid >> 5;

    const float4* xt4 = (const float4*)g_xt;

    // ---- phase 1: 144 units = (pixel, tap), one warp per unit ----
    for (int u = wi; u < 144; u += 8) {
        int p = u / 9, k = u - p * 9;
        int ly = p >> 2, lx = p & 3;
        int oh = oh0 + ly, ow = ow0 + lx;
        int di = k / 3, dj = k - di * 3;
        int dh = (di == 0) ? -1 : 0;
        int iI = (di == 0) ? 2 : (di == 1 ? 0 : 1);
        int dw = (dj == 0) ? -1 : 0;
        int jJ = (dj == 0) ? 2 : (dj == 1 ? 0 : 1);
        int h = oh + dh, w = ow + dw;
        float4* vd4 = (float4*)&v[u * 128];
        if (h < 0 || w < 0) {
            vd4[lane] = make_float4(0.f, 0.f, 0.f, 0.f);
            continue;
        }
        int n = iI * 3 + jJ;
        const float* om = &g_om[((b * Hh + h) * Ww + w) * 27];
        float offx = om[n], offy = om[9 + n], mval = om[18 + n];
        float p_x = offx + (float)(iI - 1) + (float)(h + 1);
        float p_y = offy + (float)(jJ - 1) + (float)(w + 1);
        float flx = floorf(p_x), fly = floorf(p_y);
        float ltx = fminf(fmaxf(flx, 0.f), 129.f);
        float lty = fminf(fmaxf(fly, 0.f), 129.f);
        float rbx = fminf(fmaxf(flx + 1.f, 0.f), 129.f);
        float rby = fminf(fmaxf(fly + 1.f, 0.f), 129.f);
        float cpx = fminf(fmaxf(p_x, 0.f), 129.f);
        float cpy = fminf(fmaxf(p_y, 0.f), 129.f);
        float ax  = 1.f + (ltx - cpx);
        float bx_ = 1.f - (rbx - cpx);
        float ay  = 1.f + (lty - cpy);
        float by_ = 1.f - (rby - cpy);
        float wq[4] = { ax * ay * mval, bx_ * by_ * mval, ax * by_ * mval, bx_ * ay * mval };
        float qxf[4] = { ltx, rbx, ltx, rbx };
        float qyf[4] = { lty, rby, rby, lty };
        int base4[4];
#pragma unroll
        for (int j = 0; j < 4; j++) {
            int ix = (int)qxf[j], iy = (int)qyf[j];
            bool valid = (ix >= 1 && ix <= Hh && iy >= 1 && iy <= Ww);
            base4[j] = valid ? (((b * Hh + ix - 1) * Ww + iy - 1) * 32) : 0;
            if (!valid) wq[j] = 0.f;
        }
        float4 a0 = xt4[base4[0] + lane];
        float4 a1 = xt4[base4[1] + lane];
        float4 a2 = xt4[base4[2] + lane];
        float4 a3 = xt4[base4[3] + lane];
        float4 s;
        s.x = wq[0]*a0.x + wq[1]*a1.x + wq[2]*a2.x + wq[3]*a3.x;
        s.y = wq[0]*a0.y + wq[1]*a1.y + wq[2]*a2.y + wq[3]*a3.y;
        s.z = wq[0]*a0.z + wq[1]*a1.z + wq[2]*a2.z + wq[3]*a3.z;
        s.w = wq[0]*a0.w + wq[1]*a1.w + wq[2]*a2.w + wq[3]*a3.w;
        vd4[lane] = s;
    }
    __syncthreads();

    // ---- phase 2: FFMA2 GEMM. thread = (o, pixel-group of 8) ----
    int o  = tid & 127;
    int pg = tid >> 7;  // 0 or 1

    u64 accA[8], accB[8];
#pragma unroll
    for (int q = 0; q < 8; q++) { accA[q] = 0ull; accB[q] = 0ull; }

#pragma unroll 1
    for (int k = 0; k < 9; k++) {
        const float4* wk = &g_wt4[k * 32 * 128 + o];
        u32 va = vbase + (u32)(pg * 72 + k) * 512u;   // (pg*8*9 + k)*128 floats * 4B
#pragma unroll 1
        for (int c4 = 0; c4 < 32; c4++) {
            u64 w01, w23;
            asm("ld.global.nc.v2.u64 {%0,%1}, [%2];"
                : "=l"(w01), "=l"(w23) : "l"(wk + c4 * 128));
            u32 vc = va + (u32)c4 * 16u;
#pragma unroll
            for (int q = 0; q < 8; q++) {
                u64 v01, v23;
                asm("ld.shared.v2.u64 {%0,%1}, [%2];"
                    : "=l"(v01), "=l"(v23) : "r"(vc + (u32)q * 4608u));
                asm("fma.rn.f32x2 %0, %1, %2, %0;" : "+l"(accA[q]) : "l"(v01), "l"(w01));
                asm("fma.rn.f32x2 %0, %1, %2, %0;" : "+l"(accB[q]) : "l"(v23), "l"(w23));
            }
        }
    }

    float acc[8];
#pragma unroll
    for (int q = 0; q < 8; q++) {
        float la, ha, lb, hb;
        asm("mov.b64 {%0,%1}, %2;" : "=f"(la), "=f"(ha) : "l"(accA[q]));
        asm("mov.b64 {%0,%1}, %2;" : "=f"(lb), "=f"(hb) : "l"(accB[q]));
        acc[q] = (la + ha) + (lb + hb);
    }

    int ohA = oh0 + pg * 2;
    float4 r0 = make_float4(acc[0], acc[1], acc[2], acc[3]);
    float4 r1 = make_float4(acc[4], acc[5], acc[6], acc[7]);
    *(float4*)&out[((b * OC + o) * Hh + ohA)     * Ww + ow0] = r0;
    *(float4*)&out[((b * OC + o) * Hh + ohA + 1) * Ww + ow0] = r1;
}

// ---------------------------------------------------------------
extern "C" void kernel_launch(void* const* d_in, const int* in_sizes, int n_in,
                              void* d_out, int out_size) {
    const float* x      = (const float*)d_in[0];
    const float* w_p    = (const float*)d_in[1];
    const float* b_p    = (const float*)d_in[2];
    const float* w_m    = (const float*)d_in[3];
    const float* b_m    = (const float*)d_in[4];
    const float* w_conv = (const float*)d_in[5];
    float* out = (float*)d_out;

    cudaFuncSetAttribute(k_convA,  cudaFuncAttributeMaxDynamicSharedMemorySize, (11664 + 7776) * 4);
    cudaFuncSetAttribute(k_deform, cudaFuncAttributeMaxDynamicSharedMemorySize, 18432 * 4);

    k_transpose_x<<<dim3(4, 4, Bn * Hh), dim3(32, 8)>>>(x);

    int wthreads = 9 * 32 * 128 * 4 + 27 * 9 * 128;
    k_transpose_w<<<(wthreads + 255) / 256, 256>>>(w_conv, w_p, w_m);

    k_convA<<<dim3(8, 8, Bn), 256, (11664 + 7776) * 4>>>(b_p, b_m);

    k_deform<<<dim3(32, 32, Bn), 256, 18432 * 4>>>(out);
}